// round 14
// baseline (speedup 1.0000x reference)
#include <cuda_runtime.h>
#include <cuda_bf16.h>
#include <cuda_fp16.h>
#include <cstdint>

#define N_ 16
#define C_ 128
#define H_ 128
#define W_ 128
#define HW_ (H_*W_)

// Scratch (allocation-free): add as single fp16 plane
__device__ __align__(16) __half g_h[(size_t)N_*C_*HW_];

typedef unsigned long long ull;

// ---------------------------------------------------------------------------
// helpers
// ---------------------------------------------------------------------------
__device__ __forceinline__ uint32_t smem_u32(const void* p) {
    uint32_t a;
    asm("{ .reg .u64 t; cvta.to.shared.u64 t, %1; cvt.u32.u64 %0, t; }" : "=r"(a) : "l"(p));
    return a;
}
__device__ __forceinline__ void cp16(uint32_t dst, const void* src) {
    asm volatile("cp.async.cg.shared.global [%0], [%1], 16;" :: "r"(dst), "l"(src) : "memory");
}
#define CP_COMMIT() asm volatile("cp.async.commit_group;" ::: "memory")
#define CP_WAIT(n)  asm volatile("cp.async.wait_group %0;" :: "n"(n) : "memory")

__device__ __forceinline__ void ldsm4(uint32_t* r, uint32_t a) {
    asm volatile("ldmatrix.sync.aligned.m8n8.x4.shared.b16 {%0,%1,%2,%3}, [%4];"
                 : "=r"(r[0]), "=r"(r[1]), "=r"(r[2]), "=r"(r[3]) : "r"(a));
}
__device__ __forceinline__ void ldsm4t(uint32_t* r, uint32_t a) {
    asm volatile("ldmatrix.sync.aligned.m8n8.x4.trans.shared.b16 {%0,%1,%2,%3}, [%4];"
                 : "=r"(r[0]), "=r"(r[1]), "=r"(r[2]), "=r"(r[3]) : "r"(a));
}
__device__ __forceinline__ void mma16816h(float* d, const uint32_t* a, const uint32_t* b) {
    asm volatile("mma.sync.aligned.m16n8k16.row.col.f32.f16.f16.f32 "
        "{%0,%1,%2,%3}, {%4,%5,%6,%7}, {%8,%9}, {%0,%1,%2,%3};"
        : "+f"(d[0]), "+f"(d[1]), "+f"(d[2]), "+f"(d[3])
        : "r"(a[0]), "r"(a[1]), "r"(a[2]), "r"(a[3]), "r"(b[0]), "r"(b[1]));
}
__device__ __forceinline__ uint32_t hpack(__half a, __half b) {
    uint16_t ua = *(uint16_t*)&a, ub = *(uint16_t*)&b;
    return (uint32_t)ua | ((uint32_t)ub << 16);
}
__device__ __forceinline__ ull pack2(float lo, float hi) {
    ull r;
    asm("mov.b64 %0, {%1, %2};"
        : "=l"(r) : "r"(__float_as_uint(lo)), "r"(__float_as_uint(hi)));
    return r;
}
__device__ __forceinline__ void fma2(ull& d, ull a, ull b) {
    asm("fma.rn.f32x2 %0, %1, %2, %3;" : "=l"(d) : "l"(a), "l"(b), "l"(d));
}
__device__ __forceinline__ float2 unpack2(ull v) {
    unsigned lo, hi;
    asm("mov.b64 {%0, %1}, %2;" : "=r"(lo), "=r"(hi) : "l"(v));
    return make_float2(__uint_as_float(lo), __uint_as_float(hi));
}
// pack two floats to fp16x2 (lo half = v0)
__device__ __forceinline__ uint32_t cvt_f16x2(float v0, float v1) {
    uint32_t r;
    asm("cvt.rn.f16x2.f32 %0, %1, %2;" : "=r"(r) : "f"(v1), "f"(v0));
    return r;
}

// ---------------------------------------------------------------------------
// Kernel 1: fused depthwise stack -> fp16 plane.
// EXACT round-13 version (measured ~77us): 64 threads, single band, merged acc.
// ---------------------------------------------------------------------------
__global__ __launch_bounds__(64)
void k_dw(const float* __restrict__ x,
          const float* __restrict__ w0,  const float* __restrict__ b0,
          const float* __restrict__ w01, const float* __restrict__ b01,
          const float* __restrict__ w02, const float* __restrict__ b02,
          const float* __restrict__ w11, const float* __restrict__ b11,
          const float* __restrict__ w12, const float* __restrict__ b12)
{
    __shared__ __align__(16) float sx[26][144];

    const int tid = threadIdx.x;         // 0..63
    const int h0 = blockIdx.x * 16;
    const int c  = blockIdx.y;
    const int n  = blockIdx.z;

    {
        const float* xp = x + (size_t)(n * C_ + c) * HW_;
        #pragma unroll
        for (int i = 0; i < 26; i++) {
            int gh = h0 - 5 + i;
            bool v = (gh >= 0 && gh < H_);
            sx[i][5 + tid]      = v ? xp[gh * W_ + tid] : 0.f;
            sx[i][69 + tid]     = v ? xp[gh * W_ + 64 + tid] : 0.f;
            if (tid < 5) { sx[i][tid] = 0.f; sx[i][133 + tid] = 0.f; }
        }
    }
    __syncthreads();

    ull kw0p[9], kh5p[5], kv5p[5], kh11p[11], kv11p[11];
    #pragma unroll
    for (int j = 0; j < 9; j++)  { float v = w0[c * 9 + j];  kw0p[j]  = pack2(v, v); }
    #pragma unroll
    for (int j = 0; j < 5; j++)  { float a = w01[c * 5 + j], b = w02[c * 5 + j];
                                   kh5p[j] = pack2(a, a); kv5p[j] = pack2(b, b); }
    #pragma unroll
    for (int j = 0; j < 11; j++) { float a = w11[c * 11 + j], b = w12[c * 11 + j];
                                   kh11p[j] = pack2(a, a); kv11p[j] = pack2(b, b); }
    const float cb0 = b0[c], cb01 = b01[c], cb02 = b02[c], cb11 = b11[c], cb12 = b12[c];
    const ull cb01p = pack2(cb01, cb01);
    const ull cb11p = pack2(cb11, cb11);

    ull acc[16];
    #pragma unroll
    for (int k = 0; k < 16; k++) acc[k] = 0ull;

    const int c2 = tid * 2;

    #pragma unroll
    for (int i = 0; i < 26; i++) {
        const int gh = h0 + i - 5;
        const bool valid = (gh >= 0 && gh < H_);

        float2 q[6];
        #pragma unroll
        for (int m = 0; m < 6; m++) q[m] = *(const float2*)&sx[i][c2 + 2 * m];

        ull p[11];
        #pragma unroll
        for (int m = 0; m < 6; m++) {
            if (2 * m < 11) p[2 * m] = pack2(q[m].x, q[m].y);
        }
        #pragma unroll
        for (int m = 0; m < 5; m++) p[2 * m + 1] = pack2(q[m].y, q[m + 1].x);

        ull h11 = cb11p;
        #pragma unroll
        for (int j = 0; j < 11; j++) fma2(h11, p[j], kh11p[j]);
        if (!valid) h11 = 0ull;
        #pragma unroll
        for (int k = 0; k < 16; k++) {
            if (i - k >= 0 && i - k <= 10) fma2(acc[k], h11, kv11p[i - k]);
        }

        if (i >= 3 && i <= 22) {
            ull h5 = cb01p;
            #pragma unroll
            for (int j = 0; j < 5; j++) fma2(h5, p[3 + j], kh5p[j]);
            if (!valid) h5 = 0ull;
            #pragma unroll
            for (int k = 0; k < 16; k++) {
                if (i - k >= 3 && i - k <= 7) fma2(acc[k], h5, kv5p[i - k - 3]);
            }
        }

        if (i >= 4 && i <= 21) {
            #pragma unroll
            for (int dy = 0; dy < 3; dy++) {
                const int k = i - 4 - dy;
                if (k >= 0 && k < 16) {
                    fma2(acc[k], p[4], kw0p[dy * 3 + 0]);
                    fma2(acc[k], p[5], kw0p[dy * 3 + 1]);
                    fma2(acc[k], p[6], kw0p[dy * 3 + 2]);
                }
            }
        }
    }

    const float cbs = cb0 + cb02 + cb12;
    size_t base = ((size_t)(n * C_ + c) * H_ + h0) * W_ + c2;
    #pragma unroll
    for (int k = 0; k < 16; k++) {
        float2 a = unpack2(acc[k]);
        *(uint32_t*)&g_h[base + (size_t)k * W_] = cvt_f16x2(a.x + cbs, a.y + cbs);
    }
}

// ---------------------------------------------------------------------------
// Kernel 2: mma.sync fp16 channel-mix GEMM + fused epilogue.
// Warp grid 4(m) x 4(n), warp tile 32o x 16px. A register-cached for all 8 ks
// and BOTH m-frags (64 regs) -> zero A-ldsm per tile; B-ldsm per CTA-tile
// halved vs round 12/13 (each B frag now read by 4 warps, not 8).
// ---------------------------------------------------------------------------
#define TILE_N 64
#define TPB 8
#define NSTAGE 3
#define PA 272
#define PB 144
#define SM_A    0
#define SM_B    (128*PA)                 // 34816
#define B_STAGE (128*PB)                 // 18432
#define SM_TOTAL (SM_B + NSTAGE*B_STAGE) // 90112

__device__ __forceinline__ void load_B(uint32_t sb_stage, int tid, int n, int p0) {
    const __half* hb = g_h + (size_t)n * C_ * HW_ + p0;
    #pragma unroll
    for (int i = 0; i < 2; i++) {
        int lin = i * 512 + tid;
        int c = lin >> 3, ch = lin & 7;
        cp16(sb_stage + (uint32_t)(c * PB + ch * 16), hb + (size_t)c * HW_ + ch * 8);
    }
    CP_COMMIT();
}

__global__ __launch_bounds__(512, 1)
void k_mix_mma(const float* __restrict__ x, const float* __restrict__ w3,
               const float* __restrict__ b3, float* __restrict__ out)
{
    extern __shared__ char smem[];
    const uint32_t sb = smem_u32(smem);
    const int tid  = threadIdx.x;
    const int lane = tid & 31;
    const int wid  = tid >> 5;
    const int warp_m = wid & 3;          // 4 warps over o   (32 each)
    const int warp_n = wid >> 2;         // 4 warps over px  (16 each)
    const int m0 = warp_m * 32;
    const int n0 = warp_n * 16;
    const int lm16 = lane & 15;
    const int co8  = (lane >> 4) * 8;

    // ---- load A = w3 -> smem single fp16 plane, row-major [o][c], pitch PA --
    #pragma unroll
    for (int i = 0; i < 8; i++) {
        int idx = i * 512 + tid;
        int o = idx >> 5;
        int c4 = (idx & 31) << 2;
        float4 v = *(const float4*)&w3[o * C_ + c4];
        __half h0 = __float2half_rn(v.x), h1 = __float2half_rn(v.y);
        __half h2 = __float2half_rn(v.z), h3 = __float2half_rn(v.w);
        uint32_t off = (uint32_t)(o * PA + c4 * 2);
        *(uint2*)(smem + SM_A + off) = make_uint2(hpack(h0, h1), hpack(h2, h3));
    }
    __syncthreads();

    // ---- register-cache A-frags: 8 ks x 2 m-frags (64 regs, constant) ----
    uint32_t ac[8][2][4];
    #pragma unroll
    for (int ksc = 0; ksc < 8; ksc++) {
        uint32_t arow0 = (uint32_t)((m0 + lm16) * PA + (ksc * 16 + co8) * 2);
        ldsm4(ac[ksc][0], sb + SM_A + arow0);
        ldsm4(ac[ksc][1], sb + SM_A + arow0 + 16 * PA);
    }

    float bias[2][2];
    #pragma unroll
    for (int i = 0; i < 2; i++) {
        bias[i][0] = b3[m0 + i * 16 + (lane >> 2)];
        bias[i][1] = b3[m0 + i * 16 + (lane >> 2) + 8];
    }

    // prologue: prefetch B for tiles 0 and 1
    {
        int tile0 = blockIdx.x * TPB;
        load_B(sb + SM_B + 0 * B_STAGE, tid, tile0 >> 8, (tile0 & 255) * TILE_N);
        int tile1 = tile0 + 1;
        load_B(sb + SM_B + 1 * B_STAGE, tid, tile1 >> 8, (tile1 & 255) * TILE_N);
    }

    int stage = 0;
    for (int t = 0; t < TPB; t++) {
        const int tile = blockIdx.x * TPB + t;
        const int n  = tile >> 8;
        const int p0 = (tile & 255) * TILE_N;
        const uint32_t sBst = sb + SM_B + (uint32_t)stage * B_STAGE;

        if (t < TPB - 1) { CP_WAIT(1); } else { CP_WAIT(0); }
        __syncthreads();

        if (t + 2 < TPB) {
            int nt = tile + 2;
            int nstage = stage + 2; if (nstage >= NSTAGE) nstage -= NSTAGE;
            load_B(sb + SM_B + (uint32_t)nstage * B_STAGE, tid,
                   nt >> 8, (nt & 255) * TILE_N);
        }

        float acc[2][2][4];
        #pragma unroll
        for (int i = 0; i < 2; i++)
            #pragma unroll
            for (int j = 0; j < 2; j++)
                #pragma unroll
                for (int q = 0; q < 4; q++) acc[i][j][q] = 0.f;

        #pragma unroll
        for (int ks = 0; ks < 8; ks++) {
            uint32_t bA[4];
            uint32_t brow = (uint32_t)((ks * 16 + lm16) * PB + (n0 + co8) * 2);
            ldsm4t(bA, sBst + brow);          // px n0+0 .. n0+15

            #pragma unroll
            for (int i = 0; i < 2; i++)
                #pragma unroll
                for (int j = 0; j < 2; j++)
                    mma16816h(acc[i][j], ac[ks][i], &bA[j * 2]);
        }

        // epilogue: (acc + b3) * x -> out (x loaded directly)
        #pragma unroll
        for (int i = 0; i < 2; i++) {
            #pragma unroll
            for (int j = 0; j < 2; j++) {
                int o_r = m0 + i * 16 + (lane >> 2);
                int px  = p0 + n0 + j * 8 + (lane & 3) * 2;
                size_t base0 = ((size_t)(n * C_ + o_r)) * HW_ + px;
                float2 xv0 = *(const float2*)&x[base0];
                float2 xv1 = *(const float2*)&x[base0 + 8 * HW_];
                float2 r0, r1;
                r0.x = (acc[i][j][0] + bias[i][0]) * xv0.x;
                r0.y = (acc[i][j][1] + bias[i][0]) * xv0.y;
                r1.x = (acc[i][j][2] + bias[i][1]) * xv1.x;
                r1.y = (acc[i][j][3] + bias[i][1]) * xv1.y;
                *(float2*)&out[base0]           = r0;
                *(float2*)&out[base0 + 8 * HW_] = r1;
            }
        }

        if (++stage >= NSTAGE) stage = 0;
    }
}

// ---------------------------------------------------------------------------
extern "C" void kernel_launch(void* const* d_in, const int* in_sizes, int n_in,
                              void* d_out, int out_size)
{
    const float* x   = (const float*)d_in[0];
    const float* w0  = (const float*)d_in[1];
    const float* b0  = (const float*)d_in[2];
    const float* w01 = (const float*)d_in[3];
    const float* b01 = (const float*)d_in[4];
    const float* w02 = (const float*)d_in[5];
    const float* b02 = (const float*)d_in[6];
    const float* w11 = (const float*)d_in[7];
    const float* b11 = (const float*)d_in[8];
    const float* w12 = (const float*)d_in[9];
    const float* b12 = (const float*)d_in[10];
    const float* w3  = (const float*)d_in[11];
    const float* b3  = (const float*)d_in[12];
    float* out = (float*)d_out;

    cudaFuncSetAttribute(k_mix_mma, cudaFuncAttributeMaxDynamicSharedMemorySize, SM_TOTAL);

    dim3 g1(H_ / 16, C_, N_);
    k_dw<<<g1, 64>>>(x, w0, b0, w01, b01, w02, b02, w11, b11, w12, b12);

    int tiles = N_ * (HW_ / TILE_N);        // 4096
    k_mix_mma<<<tiles / TPB, 512, SM_TOTAL>>>(x, w3, b3, out);
}

// round 15
// speedup vs baseline: 1.0378x; 1.0378x over previous
#include <cuda_runtime.h>
#include <cuda_bf16.h>
#include <cuda_fp16.h>
#include <cstdint>

#define N_ 16
#define C_ 128
#define H_ 128
#define W_ 128
#define HW_ (H_*W_)

#define NCHUNK 4
#define NB_CHUNK (N_/NCHUNK)            // 4 batches per chunk

// Scratch (allocation-free): add as single fp16 plane
__device__ __align__(16) __half g_h[(size_t)N_*C_*HW_];

typedef unsigned long long ull;

// ---------------------------------------------------------------------------
// helpers
// ---------------------------------------------------------------------------
__device__ __forceinline__ uint32_t smem_u32(const void* p) {
    uint32_t a;
    asm("{ .reg .u64 t; cvta.to.shared.u64 t, %1; cvt.u32.u64 %0, t; }" : "=r"(a) : "l"(p));
    return a;
}
__device__ __forceinline__ void cp16(uint32_t dst, const void* src) {
    asm volatile("cp.async.cg.shared.global [%0], [%1], 16;" :: "r"(dst), "l"(src) : "memory");
}
#define CP_COMMIT() asm volatile("cp.async.commit_group;" ::: "memory")
#define CP_WAIT(n)  asm volatile("cp.async.wait_group %0;" :: "n"(n) : "memory")

__device__ __forceinline__ void ldsm4(uint32_t* r, uint32_t a) {
    asm volatile("ldmatrix.sync.aligned.m8n8.x4.shared.b16 {%0,%1,%2,%3}, [%4];"
                 : "=r"(r[0]), "=r"(r[1]), "=r"(r[2]), "=r"(r[3]) : "r"(a));
}
__device__ __forceinline__ void ldsm4t(uint32_t* r, uint32_t a) {
    asm volatile("ldmatrix.sync.aligned.m8n8.x4.trans.shared.b16 {%0,%1,%2,%3}, [%4];"
                 : "=r"(r[0]), "=r"(r[1]), "=r"(r[2]), "=r"(r[3]) : "r"(a));
}
__device__ __forceinline__ void mma16816h(float* d, const uint32_t* a, const uint32_t* b) {
    asm volatile("mma.sync.aligned.m16n8k16.row.col.f32.f16.f16.f32 "
        "{%0,%1,%2,%3}, {%4,%5,%6,%7}, {%8,%9}, {%0,%1,%2,%3};"
        : "+f"(d[0]), "+f"(d[1]), "+f"(d[2]), "+f"(d[3])
        : "r"(a[0]), "r"(a[1]), "r"(a[2]), "r"(a[3]), "r"(b[0]), "r"(b[1]));
}
__device__ __forceinline__ uint32_t hpack(__half a, __half b) {
    uint16_t ua = *(uint16_t*)&a, ub = *(uint16_t*)&b;
    return (uint32_t)ua | ((uint32_t)ub << 16);
}
__device__ __forceinline__ ull pack2(float lo, float hi) {
    ull r;
    asm("mov.b64 %0, {%1, %2};"
        : "=l"(r) : "r"(__float_as_uint(lo)), "r"(__float_as_uint(hi)));
    return r;
}
__device__ __forceinline__ void fma2(ull& d, ull a, ull b) {
    asm("fma.rn.f32x2 %0, %1, %2, %3;" : "=l"(d) : "l"(a), "l"(b), "l"(d));
}
__device__ __forceinline__ float2 unpack2(ull v) {
    unsigned lo, hi;
    asm("mov.b64 {%0, %1}, %2;" : "=r"(lo), "=r"(hi) : "l"(v));
    return make_float2(__uint_as_float(lo), __uint_as_float(hi));
}
// pack two floats to fp16x2 (lo half = v0)
__device__ __forceinline__ uint32_t cvt_f16x2(float v0, float v1) {
    uint32_t r;
    asm("cvt.rn.f16x2.f32 %0, %1, %2;" : "=r"(r) : "f"(v1), "f"(v0));
    return r;
}

// ---------------------------------------------------------------------------
// Kernel 1: fused depthwise stack -> fp16 plane (round-13 body, ~77us total).
// n0 = batch offset for chunked launches.
// ---------------------------------------------------------------------------
__global__ __launch_bounds__(64)
void k_dw(const float* __restrict__ x,
          const float* __restrict__ w0,  const float* __restrict__ b0,
          const float* __restrict__ w01, const float* __restrict__ b01,
          const float* __restrict__ w02, const float* __restrict__ b02,
          const float* __restrict__ w11, const float* __restrict__ b11,
          const float* __restrict__ w12, const float* __restrict__ b12,
          int n0)
{
    __shared__ __align__(16) float sx[26][144];

    const int tid = threadIdx.x;         // 0..63
    const int h0 = blockIdx.x * 16;
    const int c  = blockIdx.y;
    const int n  = n0 + blockIdx.z;

    {
        const float* xp = x + (size_t)(n * C_ + c) * HW_;
        #pragma unroll
        for (int i = 0; i < 26; i++) {
            int gh = h0 - 5 + i;
            bool v = (gh >= 0 && gh < H_);
            sx[i][5 + tid]      = v ? xp[gh * W_ + tid] : 0.f;
            sx[i][69 + tid]     = v ? xp[gh * W_ + 64 + tid] : 0.f;
            if (tid < 5) { sx[i][tid] = 0.f; sx[i][133 + tid] = 0.f; }
        }
    }
    __syncthreads();

    ull kw0p[9], kh5p[5], kv5p[5], kh11p[11], kv11p[11];
    #pragma unroll
    for (int j = 0; j < 9; j++)  { float v = w0[c * 9 + j];  kw0p[j]  = pack2(v, v); }
    #pragma unroll
    for (int j = 0; j < 5; j++)  { float a = w01[c * 5 + j], b = w02[c * 5 + j];
                                   kh5p[j] = pack2(a, a); kv5p[j] = pack2(b, b); }
    #pragma unroll
    for (int j = 0; j < 11; j++) { float a = w11[c * 11 + j], b = w12[c * 11 + j];
                                   kh11p[j] = pack2(a, a); kv11p[j] = pack2(b, b); }
    const float cb0 = b0[c], cb01 = b01[c], cb02 = b02[c], cb11 = b11[c], cb12 = b12[c];
    const ull cb01p = pack2(cb01, cb01);
    const ull cb11p = pack2(cb11, cb11);

    ull acc[16];
    #pragma unroll
    for (int k = 0; k < 16; k++) acc[k] = 0ull;

    const int c2 = tid * 2;

    #pragma unroll
    for (int i = 0; i < 26; i++) {
        const int gh = h0 + i - 5;
        const bool valid = (gh >= 0 && gh < H_);

        float2 q[6];
        #pragma unroll
        for (int m = 0; m < 6; m++) q[m] = *(const float2*)&sx[i][c2 + 2 * m];

        ull p[11];
        #pragma unroll
        for (int m = 0; m < 6; m++) {
            if (2 * m < 11) p[2 * m] = pack2(q[m].x, q[m].y);
        }
        #pragma unroll
        for (int m = 0; m < 5; m++) p[2 * m + 1] = pack2(q[m].y, q[m + 1].x);

        ull h11 = cb11p;
        #pragma unroll
        for (int j = 0; j < 11; j++) fma2(h11, p[j], kh11p[j]);
        if (!valid) h11 = 0ull;
        #pragma unroll
        for (int k = 0; k < 16; k++) {
            if (i - k >= 0 && i - k <= 10) fma2(acc[k], h11, kv11p[i - k]);
        }

        if (i >= 3 && i <= 22) {
            ull h5 = cb01p;
            #pragma unroll
            for (int j = 0; j < 5; j++) fma2(h5, p[3 + j], kh5p[j]);
            if (!valid) h5 = 0ull;
            #pragma unroll
            for (int k = 0; k < 16; k++) {
                if (i - k >= 3 && i - k <= 7) fma2(acc[k], h5, kv5p[i - k - 3]);
            }
        }

        if (i >= 4 && i <= 21) {
            #pragma unroll
            for (int dy = 0; dy < 3; dy++) {
                const int k = i - 4 - dy;
                if (k >= 0 && k < 16) {
                    fma2(acc[k], p[4], kw0p[dy * 3 + 0]);
                    fma2(acc[k], p[5], kw0p[dy * 3 + 1]);
                    fma2(acc[k], p[6], kw0p[dy * 3 + 2]);
                }
            }
        }
    }

    const float cbs = cb0 + cb02 + cb12;
    size_t base = ((size_t)(n * C_ + c) * H_ + h0) * W_ + c2;
    #pragma unroll
    for (int k = 0; k < 16; k++) {
        float2 a = unpack2(acc[k]);
        *(uint32_t*)&g_h[base + (size_t)k * W_] = cvt_f16x2(a.x + cbs, a.y + cbs);
    }
}

// ---------------------------------------------------------------------------
// Kernel 2: mma.sync fp16 channel-mix GEMM + fused epilogue.
// Round-12 body (measured 80.4us): warp grid 8(m)x2(n), 32-reg A cache.
// tile0 = tile offset for chunked launches.
// ---------------------------------------------------------------------------
#define TILE_N 64
#define TPB 8
#define NSTAGE 3
#define PA 272
#define PB 144
#define SM_A    0
#define SM_B    (128*PA)                 // 34816
#define B_STAGE (128*PB)                 // 18432
#define SM_TOTAL (SM_B + NSTAGE*B_STAGE) // 90112

__device__ __forceinline__ void load_B(uint32_t sb_stage, int tid, int n, int p0) {
    const __half* hb = g_h + (size_t)n * C_ * HW_ + p0;
    #pragma unroll
    for (int i = 0; i < 2; i++) {
        int lin = i * 512 + tid;
        int c = lin >> 3, ch = lin & 7;
        cp16(sb_stage + (uint32_t)(c * PB + ch * 16), hb + (size_t)c * HW_ + ch * 8);
    }
    CP_COMMIT();
}

__global__ __launch_bounds__(512, 1)
void k_mix_mma(const float* __restrict__ x, const float* __restrict__ w3,
               const float* __restrict__ b3, float* __restrict__ out, int tile0)
{
    extern __shared__ char smem[];
    const uint32_t sb = smem_u32(smem);
    const int tid  = threadIdx.x;
    const int lane = tid & 31;
    const int wid  = tid >> 5;
    const int warp_m = wid & 7;          // 8 warps over o   (16 each)
    const int warp_n = wid >> 3;         // 2 warps over px  (32 each)
    const int m0 = warp_m * 16;
    const int n0 = warp_n * 32;
    const int lm16 = lane & 15;
    const int co8  = (lane >> 4) * 8;
    const int tbase = tile0 + blockIdx.x * TPB;

    // ---- load A = w3 -> smem single fp16 plane, row-major [o][c], pitch PA --
    #pragma unroll
    for (int i = 0; i < 8; i++) {
        int idx = i * 512 + tid;
        int o = idx >> 5;
        int c4 = (idx & 31) << 2;
        float4 v = *(const float4*)&w3[o * C_ + c4];
        __half h0 = __float2half_rn(v.x), h1 = __float2half_rn(v.y);
        __half h2 = __float2half_rn(v.z), h3 = __float2half_rn(v.w);
        uint32_t off = (uint32_t)(o * PA + c4 * 2);
        *(uint2*)(smem + SM_A + off) = make_uint2(hpack(h0, h1), hpack(h2, h3));
    }
    __syncthreads();

    // ---- register-cache ALL 8 ks A-frags (constant across tiles, 32 regs) --
    uint32_t ac[8][4];
    #pragma unroll
    for (int ksc = 0; ksc < 8; ksc++) {
        uint32_t arow = (uint32_t)((m0 + lm16) * PA + (ksc * 16 + co8) * 2);
        ldsm4(ac[ksc], sb + SM_A + arow);
    }

    float bias0 = b3[m0 + (lane >> 2)];
    float bias1 = b3[m0 + (lane >> 2) + 8];

    // prologue: prefetch B for tiles 0 and 1
    {
        load_B(sb + SM_B + 0 * B_STAGE, tid, tbase >> 8, (tbase & 255) * TILE_N);
        int tile1 = tbase + 1;
        load_B(sb + SM_B + 1 * B_STAGE, tid, tile1 >> 8, (tile1 & 255) * TILE_N);
    }

    int stage = 0;
    for (int t = 0; t < TPB; t++) {
        const int tile = tbase + t;
        const int n  = tile >> 8;
        const int p0 = (tile & 255) * TILE_N;
        const uint32_t sBst = sb + SM_B + (uint32_t)stage * B_STAGE;

        // prefetch epilogue x into registers
        float2 xv[4][2];
        #pragma unroll
        for (int j = 0; j < 4; j++) {
            int o_r = m0 + (lane >> 2);
            int px  = p0 + n0 + j * 8 + (lane & 3) * 2;
            size_t base0 = ((size_t)(n * C_ + o_r)) * HW_ + px;
            xv[j][0] = *(const float2*)&x[base0];
            xv[j][1] = *(const float2*)&x[base0 + 8 * HW_];
        }

        if (t < TPB - 1) { CP_WAIT(1); } else { CP_WAIT(0); }
        __syncthreads();

        if (t + 2 < TPB) {
            int nt = tile + 2;
            int nstage = stage + 2; if (nstage >= NSTAGE) nstage -= NSTAGE;
            load_B(sb + SM_B + (uint32_t)nstage * B_STAGE, tid,
                   nt >> 8, (nt & 255) * TILE_N);
        }

        float acc[4][4];
        #pragma unroll
        for (int j = 0; j < 4; j++)
            #pragma unroll
            for (int q = 0; q < 4; q++) acc[j][q] = 0.f;

        #pragma unroll
        for (int ks = 0; ks < 8; ks++) {
            uint32_t bA[4], bB[4];
            uint32_t brow = (uint32_t)((ks * 16 + lm16) * PB + (n0 + co8) * 2);
            ldsm4t(bA, sBst + brow);          // px n0+0 .. n0+15
            ldsm4t(bB, sBst + brow + 32);     // px n0+16 .. n0+31

            #pragma unroll
            for (int j = 0; j < 4; j++) {
                const uint32_t* bf = (j < 2) ? &bA[j * 2] : &bB[(j - 2) * 2];
                mma16816h(acc[j], ac[ks], bf);
            }
        }

        // epilogue: (acc + b3) * x -> out
        #pragma unroll
        for (int j = 0; j < 4; j++) {
            int o_r = m0 + (lane >> 2);
            int px  = p0 + n0 + j * 8 + (lane & 3) * 2;
            size_t base0 = ((size_t)(n * C_ + o_r)) * HW_ + px;
            float2 r0, r1;
            r0.x = (acc[j][0] + bias0) * xv[j][0].x;
            r0.y = (acc[j][1] + bias0) * xv[j][0].y;
            r1.x = (acc[j][2] + bias1) * xv[j][1].x;
            r1.y = (acc[j][3] + bias1) * xv[j][1].y;
            *(float2*)&out[base0]           = r0;
            *(float2*)&out[base0 + 8 * HW_] = r1;
        }

        if (++stage >= NSTAGE) stage = 0;
    }
}

// ---------------------------------------------------------------------------
// Launch: batch-chunk pipeline on two streams (fork/join via events — the
// standard capturable multi-stream graph pattern). Streams/events are
// intentionally NOT destroyed here: destroying a capture-participating
// stream before EndCapture is invalid. kernel_launch is called only a
// handful of times, so the leak is bounded and touches no device memory.
// ---------------------------------------------------------------------------
extern "C" void kernel_launch(void* const* d_in, const int* in_sizes, int n_in,
                              void* d_out, int out_size)
{
    const float* x   = (const float*)d_in[0];
    const float* w0  = (const float*)d_in[1];
    const float* b0  = (const float*)d_in[2];
    const float* w01 = (const float*)d_in[3];
    const float* b01 = (const float*)d_in[4];
    const float* w02 = (const float*)d_in[5];
    const float* b02 = (const float*)d_in[6];
    const float* w11 = (const float*)d_in[7];
    const float* b11 = (const float*)d_in[8];
    const float* w12 = (const float*)d_in[9];
    const float* b12 = (const float*)d_in[10];
    const float* w3  = (const float*)d_in[11];
    const float* b3  = (const float*)d_in[12];
    float* out = (float*)d_out;

    cudaFuncSetAttribute(k_mix_mma, cudaFuncAttributeMaxDynamicSharedMemorySize, SM_TOTAL);

    cudaStream_t s1;
    cudaStreamCreateWithFlags(&s1, cudaStreamNonBlocking);
    cudaEvent_t ev[NCHUNK], evf;
    for (int i = 0; i < NCHUNK; i++)
        cudaEventCreateWithFlags(&ev[i], cudaEventDisableTiming);
    cudaEventCreateWithFlags(&evf, cudaEventDisableTiming);

    const int tiles_per_chunk = NB_CHUNK * (HW_ / TILE_N);     // 1024
    const int mix_blocks = tiles_per_chunk / TPB;              // 128

    dim3 gdw(H_ / 16, C_, NB_CHUNK);
    for (int ch = 0; ch < NCHUNK; ch++) {
        k_dw<<<gdw, 64, 0, 0>>>(x, w0, b0, w01, b01, w02, b02,
                                w11, b11, w12, b12, ch * NB_CHUNK);
        cudaEventRecord(ev[ch], 0);
        cudaStreamWaitEvent(s1, ev[ch], 0);
        k_mix_mma<<<mix_blocks, 512, SM_TOTAL, s1>>>(x, w3, b3, out,
                                                     ch * tiles_per_chunk);
    }
    cudaEventRecord(evf, s1);
    cudaStreamWaitEvent(0, evf, 0);
}

// round 16
// speedup vs baseline: 1.1965x; 1.1530x over previous
#include <cuda_runtime.h>
#include <cuda_bf16.h>
#include <cuda_fp16.h>
#include <cstdint>

#define N_ 16
#define C_ 128
#define H_ 128
#define W_ 128
#define HW_ (H_*W_)

// Scratch (allocation-free): add as single fp16 plane
__device__ __align__(16) __half g_h[(size_t)N_*C_*HW_];

typedef unsigned long long ull;

// ---------------------------------------------------------------------------
// helpers
// ---------------------------------------------------------------------------
__device__ __forceinline__ uint32_t smem_u32(const void* p) {
    uint32_t a;
    asm("{ .reg .u64 t; cvta.to.shared.u64 t, %1; cvt.u32.u64 %0, t; }" : "=r"(a) : "l"(p));
    return a;
}
__device__ __forceinline__ void cp16(uint32_t dst, const void* src) {
    asm volatile("cp.async.cg.shared.global [%0], [%1], 16;" :: "r"(dst), "l"(src) : "memory");
}
#define CP_COMMIT() asm volatile("cp.async.commit_group;" ::: "memory")
#define CP_WAIT(n)  asm volatile("cp.async.wait_group %0;" :: "n"(n) : "memory")

__device__ __forceinline__ void ldsm4(uint32_t* r, uint32_t a) {
    asm volatile("ldmatrix.sync.aligned.m8n8.x4.shared.b16 {%0,%1,%2,%3}, [%4];"
                 : "=r"(r[0]), "=r"(r[1]), "=r"(r[2]), "=r"(r[3]) : "r"(a));
}
__device__ __forceinline__ void ldsm4t(uint32_t* r, uint32_t a) {
    asm volatile("ldmatrix.sync.aligned.m8n8.x4.trans.shared.b16 {%0,%1,%2,%3}, [%4];"
                 : "=r"(r[0]), "=r"(r[1]), "=r"(r[2]), "=r"(r[3]) : "r"(a));
}
__device__ __forceinline__ void mma16816h(float* d, const uint32_t* a, const uint32_t* b) {
    asm volatile("mma.sync.aligned.m16n8k16.row.col.f32.f16.f16.f32 "
        "{%0,%1,%2,%3}, {%4,%5,%6,%7}, {%8,%9}, {%0,%1,%2,%3};"
        : "+f"(d[0]), "+f"(d[1]), "+f"(d[2]), "+f"(d[3])
        : "r"(a[0]), "r"(a[1]), "r"(a[2]), "r"(a[3]), "r"(b[0]), "r"(b[1]));
}
__device__ __forceinline__ uint32_t hpack(__half a, __half b) {
    uint16_t ua = *(uint16_t*)&a, ub = *(uint16_t*)&b;
    return (uint32_t)ua | ((uint32_t)ub << 16);
}
__device__ __forceinline__ ull pack2(float lo, float hi) {
    ull r;
    asm("mov.b64 %0, {%1, %2};"
        : "=l"(r) : "r"(__float_as_uint(lo)), "r"(__float_as_uint(hi)));
    return r;
}
__device__ __forceinline__ void fma2(ull& d, ull a, ull b) {
    asm("fma.rn.f32x2 %0, %1, %2, %3;" : "=l"(d) : "l"(a), "l"(b), "l"(d));
}
__device__ __forceinline__ float2 unpack2(ull v) {
    unsigned lo, hi;
    asm("mov.b64 {%0, %1}, %2;" : "=r"(lo), "=r"(hi) : "l"(v));
    return make_float2(__uint_as_float(lo), __uint_as_float(hi));
}
// pack two floats to fp16x2 (lo half = v0)
__device__ __forceinline__ uint32_t cvt_f16x2(float v0, float v1) {
    uint32_t r;
    asm("cvt.rn.f16x2.f32 %0, %1, %2;" : "=r"(r) : "f"(v1), "f"(v0));
    return r;
}

// ---------------------------------------------------------------------------
// Kernel 1: fused depthwise stack -> fp16 plane.
// EXACT round-13 version (measured ~77us): 64 threads, single band, merged acc.
// ---------------------------------------------------------------------------
__global__ __launch_bounds__(64)
void k_dw(const float* __restrict__ x,
          const float* __restrict__ w0,  const float* __restrict__ b0,
          const float* __restrict__ w01, const float* __restrict__ b01,
          const float* __restrict__ w02, const float* __restrict__ b02,
          const float* __restrict__ w11, const float* __restrict__ b11,
          const float* __restrict__ w12, const float* __restrict__ b12)
{
    __shared__ __align__(16) float sx[26][144];

    const int tid = threadIdx.x;         // 0..63
    const int h0 = blockIdx.x * 16;
    const int c  = blockIdx.y;
    const int n  = blockIdx.z;

    {
        const float* xp = x + (size_t)(n * C_ + c) * HW_;
        #pragma unroll
        for (int i = 0; i < 26; i++) {
            int gh = h0 - 5 + i;
            bool v = (gh >= 0 && gh < H_);
            sx[i][5 + tid]      = v ? xp[gh * W_ + tid] : 0.f;
            sx[i][69 + tid]     = v ? xp[gh * W_ + 64 + tid] : 0.f;
            if (tid < 5) { sx[i][tid] = 0.f; sx[i][133 + tid] = 0.f; }
        }
    }
    __syncthreads();

    ull kw0p[9], kh5p[5], kv5p[5], kh11p[11], kv11p[11];
    #pragma unroll
    for (int j = 0; j < 9; j++)  { float v = w0[c * 9 + j];  kw0p[j]  = pack2(v, v); }
    #pragma unroll
    for (int j = 0; j < 5; j++)  { float a = w01[c * 5 + j], b = w02[c * 5 + j];
                                   kh5p[j] = pack2(a, a); kv5p[j] = pack2(b, b); }
    #pragma unroll
    for (int j = 0; j < 11; j++) { float a = w11[c * 11 + j], b = w12[c * 11 + j];
                                   kh11p[j] = pack2(a, a); kv11p[j] = pack2(b, b); }
    const float cb0 = b0[c], cb01 = b01[c], cb02 = b02[c], cb11 = b11[c], cb12 = b12[c];
    const ull cb01p = pack2(cb01, cb01);
    const ull cb11p = pack2(cb11, cb11);

    ull acc[16];
    #pragma unroll
    for (int k = 0; k < 16; k++) acc[k] = 0ull;

    const int c2 = tid * 2;

    #pragma unroll
    for (int i = 0; i < 26; i++) {
        const int gh = h0 + i - 5;
        const bool valid = (gh >= 0 && gh < H_);

        float2 q[6];
        #pragma unroll
        for (int m = 0; m < 6; m++) q[m] = *(const float2*)&sx[i][c2 + 2 * m];

        ull p[11];
        #pragma unroll
        for (int m = 0; m < 6; m++) {
            if (2 * m < 11) p[2 * m] = pack2(q[m].x, q[m].y);
        }
        #pragma unroll
        for (int m = 0; m < 5; m++) p[2 * m + 1] = pack2(q[m].y, q[m + 1].x);

        ull h11 = cb11p;
        #pragma unroll
        for (int j = 0; j < 11; j++) fma2(h11, p[j], kh11p[j]);
        if (!valid) h11 = 0ull;
        #pragma unroll
        for (int k = 0; k < 16; k++) {
            if (i - k >= 0 && i - k <= 10) fma2(acc[k], h11, kv11p[i - k]);
        }

        if (i >= 3 && i <= 22) {
            ull h5 = cb01p;
            #pragma unroll
            for (int j = 0; j < 5; j++) fma2(h5, p[3 + j], kh5p[j]);
            if (!valid) h5 = 0ull;
            #pragma unroll
            for (int k = 0; k < 16; k++) {
                if (i - k >= 3 && i - k <= 7) fma2(acc[k], h5, kv5p[i - k - 3]);
            }
        }

        if (i >= 4 && i <= 21) {
            #pragma unroll
            for (int dy = 0; dy < 3; dy++) {
                const int k = i - 4 - dy;
                if (k >= 0 && k < 16) {
                    fma2(acc[k], p[4], kw0p[dy * 3 + 0]);
                    fma2(acc[k], p[5], kw0p[dy * 3 + 1]);
                    fma2(acc[k], p[6], kw0p[dy * 3 + 2]);
                }
            }
        }
    }

    const float cbs = cb0 + cb02 + cb12;
    size_t base = ((size_t)(n * C_ + c) * H_ + h0) * W_ + c2;
    #pragma unroll
    for (int k = 0; k < 16; k++) {
        float2 a = unpack2(acc[k]);
        *(uint32_t*)&g_h[base + (size_t)k * W_] = cvt_f16x2(a.x + cbs, a.y + cbs);
    }
}

// ---------------------------------------------------------------------------
// Kernel 2: PERSISTENT mma.sync fp16 channel-mix GEMM + fused epilogue.
// Round-12 body (8m x 2n warps, 32-reg A cache). grid = #SMs (1 block/SM,
// reg-bound); each block strides tiles bx, bx+G, ... -> no wave quantization,
// A load amortized over ~27 tiles.
// ---------------------------------------------------------------------------
#define TILE_N 64
#define NTILES (N_*(HW_/TILE_N))         // 4096
#define NSTAGE 3
#define PA 272
#define PB 144
#define SM_A    0
#define SM_B    (128*PA)                 // 34816
#define B_STAGE (128*PB)                 // 18432
#define SM_TOTAL (SM_B + NSTAGE*B_STAGE) // 90112

__device__ __forceinline__ void load_B(uint32_t sb_stage, int tid, int tile) {
    const __half* hb = g_h + (size_t)(tile >> 8) * C_ * HW_ + (tile & 255) * TILE_N;
    #pragma unroll
    for (int i = 0; i < 2; i++) {
        int lin = i * 512 + tid;
        int c = lin >> 3, ch = lin & 7;
        cp16(sb_stage + (uint32_t)(c * PB + ch * 16), hb + (size_t)c * HW_ + ch * 8);
    }
    CP_COMMIT();
}

__global__ __launch_bounds__(512, 1)
void k_mix_mma(const float* __restrict__ x, const float* __restrict__ w3,
               const float* __restrict__ b3, float* __restrict__ out)
{
    extern __shared__ char smem[];
    const uint32_t sb = smem_u32(smem);
    const int tid  = threadIdx.x;
    const int lane = tid & 31;
    const int wid  = tid >> 5;
    const int warp_m = wid & 7;          // 8 warps over o   (16 each)
    const int warp_n = wid >> 3;         // 2 warps over px  (32 each)
    const int m0 = warp_m * 16;
    const int n0 = warp_n * 32;
    const int lm16 = lane & 15;
    const int co8  = (lane >> 4) * 8;
    const int bx = blockIdx.x;
    const int G  = gridDim.x;
    const int niter = (NTILES - bx + G - 1) / G;

    // ---- load A = w3 -> smem single fp16 plane, row-major [o][c], pitch PA --
    #pragma unroll
    for (int i = 0; i < 8; i++) {
        int idx = i * 512 + tid;
        int o = idx >> 5;
        int c4 = (idx & 31) << 2;
        float4 v = *(const float4*)&w3[o * C_ + c4];
        __half h0 = __float2half_rn(v.x), h1 = __float2half_rn(v.y);
        __half h2 = __float2half_rn(v.z), h3 = __float2half_rn(v.w);
        uint32_t off = (uint32_t)(o * PA + c4 * 2);
        *(uint2*)(smem + SM_A + off) = make_uint2(hpack(h0, h1), hpack(h2, h3));
    }
    __syncthreads();

    // ---- register-cache ALL 8 ks A-frags (constant across tiles, 32 regs) --
    uint32_t ac[8][4];
    #pragma unroll
    for (int ksc = 0; ksc < 8; ksc++) {
        uint32_t arow = (uint32_t)((m0 + lm16) * PA + (ksc * 16 + co8) * 2);
        ldsm4(ac[ksc], sb + SM_A + arow);
    }

    float bias0 = b3[m0 + (lane >> 2)];
    float bias1 = b3[m0 + (lane >> 2) + 8];

    // prologue: prefetch B for first two assigned tiles
    load_B(sb + SM_B + 0 * B_STAGE, tid, bx);
    if (niter > 1) load_B(sb + SM_B + 1 * B_STAGE, tid, bx + G);

    int stage = 0;
    for (int t = 0; t < niter; t++) {
        const int tile = bx + t * G;
        const int n  = tile >> 8;
        const int p0 = (tile & 255) * TILE_N;
        const uint32_t sBst = sb + SM_B + (uint32_t)stage * B_STAGE;

        // prefetch epilogue x into registers
        float2 xv[4][2];
        #pragma unroll
        for (int j = 0; j < 4; j++) {
            int o_r = m0 + (lane >> 2);
            int px  = p0 + n0 + j * 8 + (lane & 3) * 2;
            size_t base0 = ((size_t)(n * C_ + o_r)) * HW_ + px;
            xv[j][0] = *(const float2*)&x[base0];
            xv[j][1] = *(const float2*)&x[base0 + 8 * HW_];
        }

        if (t < niter - 1) { CP_WAIT(1); } else { CP_WAIT(0); }
        __syncthreads();

        if (t + 2 < niter) {
            int nstage = stage + 2; if (nstage >= NSTAGE) nstage -= NSTAGE;
            load_B(sb + SM_B + (uint32_t)nstage * B_STAGE, tid, tile + 2 * G);
        }

        float acc[4][4];
        #pragma unroll
        for (int j = 0; j < 4; j++)
            #pragma unroll
            for (int q = 0; q < 4; q++) acc[j][q] = 0.f;

        #pragma unroll
        for (int ks = 0; ks < 8; ks++) {
            uint32_t bA[4], bB[4];
            uint32_t brow = (uint32_t)((ks * 16 + lm16) * PB + (n0 + co8) * 2);
            ldsm4t(bA, sBst + brow);          // px n0+0 .. n0+15
            ldsm4t(bB, sBst + brow + 32);     // px n0+16 .. n0+31

            #pragma unroll
            for (int j = 0; j < 4; j++) {
                const uint32_t* bf = (j < 2) ? &bA[j * 2] : &bB[(j - 2) * 2];
                mma16816h(acc[j], ac[ks], bf);
            }
        }

        // epilogue: (acc + b3) * x -> out
        #pragma unroll
        for (int j = 0; j < 4; j++) {
            int o_r = m0 + (lane >> 2);
            int px  = p0 + n0 + j * 8 + (lane & 3) * 2;
            size_t base0 = ((size_t)(n * C_ + o_r)) * HW_ + px;
            float2 r0, r1;
            r0.x = (acc[j][0] + bias0) * xv[j][0].x;
            r0.y = (acc[j][1] + bias0) * xv[j][0].y;
            r1.x = (acc[j][2] + bias1) * xv[j][1].x;
            r1.y = (acc[j][3] + bias1) * xv[j][1].y;
            *(float2*)&out[base0]           = r0;
            *(float2*)&out[base0 + 8 * HW_] = r1;
        }

        if (++stage >= NSTAGE) stage = 0;
    }
}

// ---------------------------------------------------------------------------
extern "C" void kernel_launch(void* const* d_in, const int* in_sizes, int n_in,
                              void* d_out, int out_size)
{
    const float* x   = (const float*)d_in[0];
    const float* w0  = (const float*)d_in[1];
    const float* b0  = (const float*)d_in[2];
    const float* w01 = (const float*)d_in[3];
    const float* b01 = (const float*)d_in[4];
    const float* w02 = (const float*)d_in[5];
    const float* b02 = (const float*)d_in[6];
    const float* w11 = (const float*)d_in[7];
    const float* b11 = (const float*)d_in[8];
    const float* w12 = (const float*)d_in[9];
    const float* b12 = (const float*)d_in[10];
    const float* w3  = (const float*)d_in[11];
    const float* b3  = (const float*)d_in[12];
    float* out = (float*)d_out;

    cudaFuncSetAttribute(k_mix_mma, cudaFuncAttributeMaxDynamicSharedMemorySize, SM_TOTAL);

    int nsm = 148;
    cudaDeviceGetAttribute(&nsm, cudaDevAttrMultiProcessorCount, 0);

    dim3 g1(H_ / 16, C_, N_);
    k_dw<<<g1, 64>>>(x, w0, b0, w01, b01, w02, b02, w11, b11, w12, b12);

    k_mix_mma<<<nsm, 512, SM_TOTAL>>>(x, w3, b3, out);
}